// round 6
// baseline (speedup 1.0000x reference)
#include <cuda_runtime.h>
#include <cuda_bf16.h>

// Problem constants (VOCAB=32000, D_MODEL=512, BATCH=8, SEQ=4096)
constexpr int B_ = 8;
constexpr int S_ = 4096;
constexpr int D_ = 512;
constexpr int BPB = 4;                  // batch rows per block (grid.y = B_/BPB)

// pe[s,d] = sin(angle) for even d, cos(angle) for odd d,
// angle = s / 10000^(2d/512)  (per-index exponent, faithful to reference)
__device__ __forceinline__ float pe_val(float sf, int d) {
    const float C       = -0.05190512648261504f;  // -2/512 * log2(10000)
    const float INV2PI  =  0.15915494309189535f;
    const float PI2_HI  =  6.2831855f;            // fl32(2*pi)
    const float PI2_LO  = -1.7484556e-7f;         // 2*pi - PI2_HI
    const float PIO2    =  1.5707963267948966f;

    float w   = exp2f((float)d * C);              // 10000^(-2d/512)
    float off = (d & 1) ? PIO2 : 0.0f;            // odd d -> cos = sin(x + pi/2)
    float ang = fmaf(sf, w, off);
    float k   = rintf(ang * INV2PI);
    float r   = fmaf(k, -PI2_HI, ang);
    r         = fmaf(k, -PI2_LO, r);
    return __sinf(r);                             // |r| <= pi -> accurate
}

__global__ __launch_bounds__(128, 12) void emb_pe_kernel(
    const int*   __restrict__ tokens,   // [B, S]
    const float* __restrict__ table,    // [V, D]
    float*       __restrict__ out)      // [B, S, D]
{
    const int s  = blockIdx.x;          // 0..4095
    const int b0 = blockIdx.y * BPB;    // 0 or 4
    const int t  = threadIdx.x;         // 0..127

    // Uniform token loads (same address across warp -> broadcast). Only 4 per
    // block now: fewer live regs, dependent chain unchanged.
    int tok[BPB];
    #pragma unroll
    for (int b = 0; b < BPB; b++)
        tok[b] = __ldg(tokens + (b0 + b) * S_ + s);

    // Issue all 4 row gathers before touching the data (MLP = 4/thread,
    // but ~48 warps/SM resident -> ~192 LDG.128 in flight per SM).
    const float4* __restrict__ tab4 = reinterpret_cast<const float4*>(table);
    float4 v[BPB];
    #pragma unroll
    for (int b = 0; b < BPB; b++)
        v[b] = __ldg(tab4 + (size_t)tok[b] * (D_ / 4) + t);

    // Trig overlaps the in-flight gathers (batch-invariant per s).
    const float sf = (float)s;
    const int d0 = t * 4;
    float4 pe4;
    pe4.x = pe_val(sf, d0 + 0);
    pe4.y = pe_val(sf, d0 + 1);
    pe4.z = pe_val(sf, d0 + 2);
    pe4.w = pe_val(sf, d0 + 3);

    // Add + streaming store (.cs: output never re-read; keep table in L2).
    float4* __restrict__ out4 = reinterpret_cast<float4*>(out);
    #pragma unroll
    for (int b = 0; b < BPB; b++) {
        float4 r = v[b];
        r.x += pe4.x;
        r.y += pe4.y;
        r.z += pe4.z;
        r.w += pe4.w;
        __stcs(out4 + ((size_t)(b0 + b) * S_ + s) * (D_ / 4) + t, r);
    }
}

extern "C" void kernel_launch(void* const* d_in, const int* in_sizes, int n_in,
                              void* d_out, int out_size) {
    const int*   tokens = (const int*)d_in[0];     // [8, 4096] int32
    const float* table  = (const float*)d_in[1];   // [32000, 512] float32
    float*       out    = (float*)d_out;           // [8, 4096, 512] float32
    (void)in_sizes; (void)n_in; (void)out_size;

    dim3 grid(S_, B_ / BPB);
    emb_pe_kernel<<<grid, 128>>>(tokens, table, out);
}

// round 7
// speedup vs baseline: 1.0271x; 1.0271x over previous
#include <cuda_runtime.h>
#include <cuda_bf16.h>
#include <cstdint>

// Problem constants (VOCAB=32000, D_MODEL=512, BATCH=8, SEQ=4096)
constexpr int B_ = 8;
constexpr int S_ = 4096;
constexpr int D_ = 512;

// pe[s,d] = sin(angle) for even d, cos(angle) for odd d,
// angle = s / 10000^(2d/512)  (per-index exponent, faithful to reference)
__device__ __forceinline__ float pe_val(float sf, int d) {
    const float C       = -0.05190512648261504f;  // -2/512 * log2(10000)
    const float INV2PI  =  0.15915494309189535f;
    const float PI2_HI  =  6.2831855f;            // fl32(2*pi)
    const float PI2_LO  = -1.7484556e-7f;         // 2*pi - PI2_HI
    const float PIO2    =  1.5707963267948966f;

    float w   = exp2f((float)d * C);              // 10000^(-2d/512)
    float off = (d & 1) ? PIO2 : 0.0f;            // odd d -> cos = sin(x + pi/2)
    float ang = fmaf(sf, w, off);
    float k   = rintf(ang * INV2PI);
    float r   = fmaf(k, -PI2_HI, ang);
    r         = fmaf(k, -PI2_LO, r);
    return __sinf(r);                             // |r| <= pi -> accurate
}

__device__ __forceinline__ uint32_t smem_u32(const void* p) {
    uint32_t a;
    asm("{ .reg .u64 t; cvta.to.shared.u64 t, %1; cvt.u32.u64 %0, t; }"
        : "=r"(a) : "l"(p));
    return a;
}

__global__ __launch_bounds__(128) void emb_pe_kernel(
    const int*   __restrict__ tokens,   // [B, S]
    const float* __restrict__ table,    // [V, D]
    float*       __restrict__ out)      // [B, S, D]
{
    const int s = blockIdx.x;           // 0..4095
    const int t = threadIdx.x;          // 0..127

    __shared__ __align__(128) float4 obuf[B_][D_ / 4];   // 16 KB staging

    // Uniform token loads (broadcast across the warp; no smem, no barrier on
    // the critical gather path).
    int tok[B_];
    #pragma unroll
    for (int b = 0; b < B_; b++)
        tok[b] = __ldg(tokens + b * S_ + s);

    // Issue all 8 row gathers (MLP = 8 per thread) before touching the data.
    const float4* __restrict__ tab4 = reinterpret_cast<const float4*>(table);
    float4 v[B_];
    #pragma unroll
    for (int b = 0; b < B_; b++)
        v[b] = __ldg(tab4 + (size_t)tok[b] * (D_ / 4) + t);

    // Trig overlaps the in-flight gathers (batch-invariant per s).
    const float sf = (float)s;
    const int d0 = t * 4;
    float4 pe4;
    pe4.x = pe_val(sf, d0 + 0);
    pe4.y = pe_val(sf, d0 + 1);
    pe4.z = pe_val(sf, d0 + 2);
    pe4.w = pe_val(sf, d0 + 3);

    // Add + stage into smem (STS.128: smem crossbar, NOT the L1tex wavefront
    // path the gathers are using).
    #pragma unroll
    for (int b = 0; b < B_; b++) {
        float4 r = v[b];
        r.x += pe4.x;
        r.y += pe4.y;
        r.z += pe4.z;
        r.w += pe4.w;
        obuf[b][t] = r;
    }
    __syncthreads();

    // One thread emits the 8 output rows as 2KB bulk copies smem -> global
    // (async proxy: bypasses per-thread STG / L1tex wavefronts entirely).
    if (t == 0) {
        asm volatile("fence.proxy.async.shared::cta;" ::: "memory");
        #pragma unroll
        for (int b = 0; b < B_; b++) {
            float* gdst = out + ((size_t)b * S_ + s) * D_;
            uint32_t ssrc = smem_u32(&obuf[b][0]);
            asm volatile(
                "cp.async.bulk.global.shared::cta.bulk_group [%0], [%1], %2;"
                :: "l"(gdst), "r"(ssrc), "r"(D_ * 4) : "memory");
        }
        asm volatile("cp.async.bulk.commit_group;" ::: "memory");
        // Drain before smem can be reused by the next block on this SM.
        asm volatile("cp.async.bulk.wait_group 0;" ::: "memory");
    }
}

extern "C" void kernel_launch(void* const* d_in, const int* in_sizes, int n_in,
                              void* d_out, int out_size) {
    const int*   tokens = (const int*)d_in[0];     // [8, 4096] int32
    const float* table  = (const float*)d_in[1];   // [32000, 512] float32
    float*       out    = (float*)d_out;           // [8, 4096, 512] float32
    (void)in_sizes; (void)n_in; (void)out_size;

    emb_pe_kernel<<<S_, 128>>>(tokens, table, out);
}

// round 10
// speedup vs baseline: 1.3846x; 1.3481x over previous
#include <cuda_runtime.h>
#include <cuda_bf16.h>
#include <cstdint>

// Problem constants (VOCAB=32000, D_MODEL=512, BATCH=8, SEQ=4096)
constexpr int B_ = 8;
constexpr int S_ = 4096;
constexpr int D_ = 512;

// pe[s,d] = sin(angle) for even d, cos(angle) for odd d,
// angle = s / 10000^(2d/512)  (per-index exponent, faithful to reference)
__device__ __forceinline__ float pe_val(float sf, int d) {
    const float C       = -0.05190512648261504f;  // -2/512 * log2(10000)
    const float INV2PI  =  0.15915494309189535f;
    const float PI2_HI  =  6.2831855f;            // fl32(2*pi)
    const float PI2_LO  = -1.7484556e-7f;         // 2*pi - PI2_HI
    const float PIO2    =  1.5707963267948966f;

    float w   = exp2f((float)d * C);              // 10000^(-2d/512)
    float off = (d & 1) ? PIO2 : 0.0f;            // odd d -> cos = sin(x + pi/2)
    float ang = fmaf(sf, w, off);
    float k   = rintf(ang * INV2PI);
    float r   = fmaf(k, -PI2_HI, ang);
    r         = fmaf(k, -PI2_LO, r);
    return __sinf(r);                             // |r| <= pi -> accurate
}

// 16B gather with an L2 evict-last cache-policy operand (the form ptxas
// accepts on sm_103 for sub-32B loads).
__device__ __forceinline__ float4 ldg_el(const float4* p, uint64_t pol) {
    float4 v;
    asm volatile("ld.global.nc.L2::cache_hint.v4.f32 {%0,%1,%2,%3}, [%4], %5;"
                 : "=f"(v.x), "=f"(v.y), "=f"(v.z), "=f"(v.w)
                 : "l"(p), "l"(pol));
    return v;
}

__global__ __launch_bounds__(256) void emb_pe_kernel(
    const int*   __restrict__ tokens,   // [B, S]
    const float* __restrict__ table,    // [V, D]
    float*       __restrict__ out)      // [B, S, D]
{
    // 2 s-values per 256-thread block; threads 0..127 -> s0, 128..255 -> s0+1.
    const int s = blockIdx.x * 2 + (threadIdx.x >> 7);
    const int t = threadIdx.x & 127;

    // Table lines get evict-last priority in L2 (vs .cs evict-first output).
    uint64_t pol;
    asm("createpolicy.fractional.L2::evict_last.b64 %0, 1.0;" : "=l"(pol));

    // Uniform token loads (broadcast within each warp; no smem, no barrier).
    int tok[B_];
    #pragma unroll
    for (int b = 0; b < B_; b++)
        tok[b] = __ldg(tokens + b * S_ + s);

    // Issue all 8 row gathers (MLP = 8 per thread) before touching the data.
    const float4* __restrict__ tab4 = reinterpret_cast<const float4*>(table);
    float4 v[B_];
    #pragma unroll
    for (int b = 0; b < B_; b++)
        v[b] = ldg_el(tab4 + (size_t)tok[b] * (D_ / 4) + t, pol);

    // Trig overlaps the in-flight gathers (batch-invariant per s).
    const float sf = (float)s;
    const int d0 = t * 4;
    float4 pe4;
    pe4.x = pe_val(sf, d0 + 0);
    pe4.y = pe_val(sf, d0 + 1);
    pe4.z = pe_val(sf, d0 + 2);
    pe4.w = pe_val(sf, d0 + 3);

    // Add + streaming store (.cs evict-first: never contests table residency).
    float4* __restrict__ out4 = reinterpret_cast<float4*>(out);
    #pragma unroll
    for (int b = 0; b < B_; b++) {
        float4 r = v[b];
        r.x += pe4.x;
        r.y += pe4.y;
        r.z += pe4.z;
        r.w += pe4.w;
        __stcs(out4 + ((size_t)b * S_ + s) * (D_ / 4) + t, r);
    }
}

extern "C" void kernel_launch(void* const* d_in, const int* in_sizes, int n_in,
                              void* d_out, int out_size) {
    const int*   tokens = (const int*)d_in[0];     // [8, 4096] int32
    const float* table  = (const float*)d_in[1];   // [32000, 512] float32
    float*       out    = (float*)d_out;           // [8, 4096, 512] float32
    (void)in_sizes; (void)n_in; (void)out_size;

    emb_pe_kernel<<<S_ / 2, 256>>>(tokens, table, out);
}